// round 5
// baseline (speedup 1.0000x reference)
#include <cuda_runtime.h>
#include <cstdint>

#define BT20   2621440u     // B*20 (elements per head slab)
#define HALFN  52428800u
#define NROWS  131072u
#define TPB    64
#define ATPB   256

__device__ uint32_t g_mask[40u * NROWS];   // bit o of word [k*NROWS+b] = keep(k,b,o)

// ---- packed f32x2 helpers ----
__device__ __forceinline__ unsigned long long pack2(float lo, float hi) {
    unsigned long long r;
    asm("mov.b64 %0, {%1, %2};" : "=l"(r) : "f"(lo), "f"(hi));
    return r;
}
__device__ __forceinline__ void unpack2(unsigned long long v, float &lo, float &hi) {
    asm("mov.b64 {%0, %1}, %2;" : "=f"(lo), "=f"(hi) : "l"(v));
}
__device__ __forceinline__ void fma2(unsigned long long &d, unsigned long long a,
                                     unsigned long long b) {
    asm("fma.rn.f32x2 %0, %1, %2, %0;" : "+l"(d) : "l"(a), "l"(b));
}
__device__ __forceinline__ void add2(unsigned long long &d, unsigned long long a) {
    asm("add.rn.f32x2 %0, %0, %1;" : "+l"(d) : "l"(a));
}
__device__ __forceinline__ unsigned long long f2lo(const float4 &v) { return pack2(v.x, v.y); }
__device__ __forceinline__ unsigned long long f2hi(const float4 &v) { return pack2(v.z, v.w); }

// integer add on the FMA pipe (IMAD); 'one' is runtime-opaque
__device__ __forceinline__ uint32_t addm(uint32_t a, uint32_t b, uint32_t one) {
    uint32_t r;
    asm("mad.lo.u32 %0, %1, %2, %3;" : "=r"(r) : "r"(b), "r"(one), "r"(a));
    return r;
}
__device__ __forceinline__ uint32_t mullo(uint32_t a, uint32_t b) {
    uint32_t r; asm("mul.lo.u32 %0, %1, %2;" : "=r"(r) : "r"(a), "r"(b)); return r;
}
__device__ __forceinline__ uint32_t mulhi_(uint32_t a, uint32_t b) {
    uint32_t r; asm("mul.hi.u32 %0, %1, %2;" : "=r"(r) : "r"(a), "r"(b)); return r;
}

// ---- Threefry-2x32-20, key (0,42); returns ~(o0^o1) (XNOR) ----
// 'one' = 1 (runtime), 'c13' = 1<<13 (runtime) keep IMADs on the fma pipe.
__device__ __forceinline__ uint32_t tf_xnor(uint32_t x1_init, uint32_t one, uint32_t c13) {
    const uint32_t ks1 = 42u;
    const uint32_t ks2 = 0x1BD11BDAu ^ 42u;
    uint32_t x0 = 0u;
    uint32_t x1 = x1_init;        // = j + ks1 (precomputed by caller)
#define TF_R(r)  { x0 = addm(x0, x1, one); \
                   x1 = __funnelshift_l(x1, x1, (r)); x1 ^= x0; }
// multiply-form rotate-13 round: 2 IMAD (fma pipe) + 1 fused LOP3
#define TF_R13M  { x0 = addm(x0, x1, one); \
                   uint32_t lo_ = mullo(x1, c13), hi_ = mulhi_(x1, c13); \
                   x1 = (lo_ | hi_) ^ x0; }
    TF_R13M        TF_R(15) TF_R(26) TF_R(6)
    x0 = addm(x0, one*ks1, one);  x1 = addm(x1, one*(ks2 + 1u), one);
    TF_R(17) TF_R(29) TF_R(16) TF_R(24)
    x0 = addm(x0, one*ks2, one);  x1 = addm(x1, one*2u, one);
    TF_R13M        TF_R(15) TF_R(26) TF_R(6)
    x1 = addm(x1, one*(ks1 + 3u), one);
    TF_R(17) TF_R(29) TF_R(16) TF_R(24)
    x0 = addm(x0, one*ks1, one);  x1 = addm(x1, one*(ks2 + 4u), one);
    TF_R13M        TF_R(15) TF_R(26) TF_R(6)
    x0 = addm(x0, one*ks2, one);  x1 = addm(x1, one*5u, one);
#undef TF_R
#undef TF_R13M
    return ~(x0 ^ x1);   // keep-bit in MSB (keep iff sample MSB == 0)
}

// ================= Kernel A: mask generation =================
__global__ __launch_bounds__(ATPB)
void mask_kernel(uint32_t one) {
    const unsigned idx = blockIdx.x * ATPB + threadIdx.x;   // k*NROWS + b
    const unsigned k = idx >> 17;
    const unsigned b = idx & (NROWS - 1u);
    const uint32_t c13 = one << 13;
    const uint32_t jk = k * BT20 + b * 20u + 42u;           // j + ks1 base
    uint32_t w = 0u;
    #pragma unroll
    for (int o = 0; o < 20; o++) {
        uint32_t t = tf_xnor(addm(jk, one*(uint32_t)o, one), one, c13);
        uint32_t bit = t >> 31;
        asm("mad.lo.u32 %0, %1, %2, %0;" : "+r"(w) : "r"(bit), "r"(one << o));
    }
    g_mask[idx] = w;
}

// ================= Kernel B: fused MLP + mask apply =================
__global__ __launch_bounds__(TPB, 8)
void mlp_kernel(const float* __restrict__ x,
                const float* __restrict__ W1,
                const float* __restrict__ b1,
                const float* __restrict__ Wh,
                const float* __restrict__ bh,
                float* __restrict__ out)
{
    __shared__ __align__(16) float sW1[1200];   // [60][20]
    __shared__           float sb1[64];
    __shared__ __align__(16) float sbh[800];    // [40][20]
    __shared__ __align__(16) float sWhA[1200];  // Wh[k]      [20][60]
    __shared__ __align__(16) float sWhB[1200];  // Wh[k+20]   [20][60]

    const int tid = threadIdx.x;

    for (int i = tid; i < 300; i += TPB)
        ((float4*)sW1)[i] = ((const float4*)W1)[i];
    for (int i = tid; i < 200; i += TPB)
        ((float4*)sbh)[i] = ((const float4*)bh)[i];
    if (tid < 60) sb1[tid] = b1[tid];
    __syncthreads();

    const unsigned b = blockIdx.x * TPB + tid;   // one row per thread

    unsigned long long x2[10];
    {
        const float4* xp = (const float4*)(x + (size_t)b * 20);
        #pragma unroll
        for (int i = 0; i < 5; i++) {
            float4 v = xp[i];
            x2[2*i]   = f2lo(v);
            x2[2*i+1] = f2hi(v);
        }
    }

    // trunk: h = relu(W1 @ x + b1) as 30 f32x2 regs
    unsigned long long h2[30];
    #pragma unroll
    for (int i = 0; i < 30; i++) {
        unsigned long long a0 = 0ull, a1 = 0ull;
        const float4* w0 = (const float4*)(sW1 + (2*i)   * 20);
        const float4* w1 = (const float4*)(sW1 + (2*i+1) * 20);
        #pragma unroll
        for (int d = 0; d < 5; d++) {
            float4 v0 = w0[d], v1 = w1[d];
            fma2(a0, x2[2*d],   f2lo(v0));
            fma2(a0, x2[2*d+1], f2hi(v0));
            fma2(a1, x2[2*d],   f2lo(v1));
            fma2(a1, x2[2*d+1], f2hi(v1));
        }
        float s0a, s0b, s1a, s1b;
        unpack2(a0, s0a, s0b);
        unpack2(a1, s1a, s1b);
        h2[i] = pack2(fmaxf(s0a + s0b + sb1[2*i],   0.f),
                      fmaxf(s1a + s1b + sb1[2*i+1], 0.f));
    }

    const unsigned base_b = b * 20u;

    for (int k = 0; k < 20; k++) {
        // masks for this k-pair (LDG latency hides under staging + GEMM)
        const uint32_t mA = g_mask[(unsigned)k        * NROWS + b];
        const uint32_t mB = g_mask[(unsigned)(k + 20) * NROWS + b];

        __syncthreads();   // protect previous iteration's sWh reads
        const float4* srcA = (const float4*)(Wh + (size_t)k        * 1200);
        const float4* srcB = (const float4*)(Wh + (size_t)(k + 20) * 1200);
        for (int i = tid; i < 300; i += TPB) {
            ((float4*)sWhA)[i] = srcA[i];
            ((float4*)sWhB)[i] = srcB[i];
        }
        __syncthreads();

        #pragma unroll 1
        for (int oc = 0; oc < 5; oc++) {
            float y0v[4], y1v[4];
            #pragma unroll
            for (int u = 0; u < 4; u++) {
                const int o = oc * 4 + u;
                const float4* wA4 = (const float4*)(sWhA + o * 60);
                const float4* wB4 = (const float4*)(sWhB + o * 60);
                unsigned long long a0 = 0ull, a0b = 0ull, a1 = 0ull, a1b = 0ull;
                #pragma unroll
                for (int d = 0; d < 15; d++) {
                    float4 va = wA4[d];
                    float4 vb = wB4[d];
                    fma2(a0,  f2lo(va), h2[2*d]);
                    fma2(a0b, f2hi(va), h2[2*d+1]);
                    fma2(a1,  f2lo(vb), h2[2*d]);
                    fma2(a1b, f2hi(vb), h2[2*d+1]);
                }
                add2(a0, a0b);
                add2(a1, a1b);
                float pA, qA, pB, qB;
                unpack2(a0, pA, qA);
                unpack2(a1, pB, qB);
                float accA = (pA + qA) + sbh[k*20 + o];
                float accB = (pB + qB) + sbh[(k+20)*20 + o];

                // keep-multiplier 2.0f / 0.0f from mask bit o (alu-pipe ops)
                float fA = __uint_as_float(
                    (uint32_t)((int)(mA << (31 - o)) >> 31) & 0x40000000u);
                float fB = __uint_as_float(
                    (uint32_t)((int)(mB << (31 - o)) >> 31) & 0x40000000u);
                y0v[u] = fmaxf(accA, 0.f) * fA;
                y1v[u] = fmaxf(accB, 0.f) * fB;
            }
            float4 v0 = make_float4(y0v[0], y0v[1], y0v[2], y0v[3]);
            float4 v1 = make_float4(y1v[0], y1v[1], y1v[2], y1v[3]);
            *(float4*)(out + (size_t)k        * BT20 + base_b + oc * 4) = v0;
            *(float4*)(out + (size_t)(k + 20) * BT20 + base_b + oc * 4) = v1;
        }
    }
}

extern "C" void kernel_launch(void* const* d_in, const int* in_sizes, int n_in,
                              void* d_out, int out_size) {
    const float* x  = (const float*)d_in[0];   // [131072, 20]
    const float* W1 = (const float*)d_in[1];   // [60, 20]
    const float* b1 = (const float*)d_in[2];   // [60]
    const float* Wh = (const float*)d_in[3];   // [40, 20, 60]
    const float* bh = (const float*)d_in[4];   // [40, 20]
    float* out = (float*)d_out;                // [40, 131072, 1, 20]

    const int rows = in_sizes[0] / 20;         // 131072
    mask_kernel<<<(40u * NROWS) / ATPB, ATPB>>>(1u);
    mlp_kernel<<<rows / TPB, TPB>>>(x, W1, b1, Wh, bh, out);
}